// round 6
// baseline (speedup 1.0000x reference)
#include <cuda_runtime.h>
#include <math.h>

#define NPRE   1024
#define NPOST  256
#define MAXB   128

// scan kernel geometry: warp owns 4 neurons x 8 k-slices
#define CH     64                 // k-chunk length
#define NSUB   8                  // slices per chunk
#define KSUB   (CH / NSUB)        // 8 k per slice
#define NTHR   512                // 16 warps -> 64 neurons per block
#define NT     64
#define NGRP   (NPOST / NT)       // 4 neuron groups per batch
#define NCHUNK (NPRE / CH)        // 16 chunks
#define FULL   0xffffffffu

#define INV_E_F  0.36787944117144233f
#define E_F      2.718281828459045f

// Scratch (no allocations allowed): sorted spike data per batch row.
__device__ float g_sorted[MAXB * NPRE];
__device__ float g_exp[MAXB * NPRE];   // exp(s)
__device__ float g_se[MAXB * NPRE];    // s * exp(s)
__device__ int   g_idx[MAXB * NPRE];   // argsort indices

// ---------------------------------------------------------------------------
// Kernel 1: stable ascending sort of each batch row (matches jnp.argsort).
// (verified since R4)
// ---------------------------------------------------------------------------
__global__ void __launch_bounds__(512) sort_kernel(const float* __restrict__ spikes)
{
    __shared__ unsigned long long keys[NPRE];
    const int b   = blockIdx.x;
    const int tid = threadIdx.x;

    for (int i = tid; i < NPRE; i += 512) {
        float v = spikes[b * NPRE + i];
        unsigned int bits = __float_as_uint(v);
        bits = (bits & 0x80000000u) ? ~bits : (bits | 0x80000000u);
        keys[i] = ((unsigned long long)bits << 32) | (unsigned int)i;
    }
    __syncthreads();

    for (int k = 2; k <= NPRE; k <<= 1) {
        for (int j = k >> 1; j >= 32; j >>= 1) {
            #pragma unroll
            for (int rep = 0; rep < NPRE / 512; ++rep) {
                int i = tid + rep * 512;
                int ixj = i ^ j;
                if (ixj > i) {
                    unsigned long long A = keys[i];
                    unsigned long long C = keys[ixj];
                    bool up = ((i & k) == 0);
                    if ((A > C) == up) { keys[i] = C; keys[ixj] = A; }
                }
            }
            __syncthreads();
        }
        unsigned long long v0 = keys[tid];
        unsigned long long v1 = keys[tid + 512];
        const bool up0 = ((tid & k) == 0);
        const bool up1 = (((tid + 512) & k) == 0);
        #pragma unroll
        for (int j = 16; j >= 1; j >>= 1) {
            if (j < k) {
                bool lower = ((tid & j) == 0);
                unsigned long long p0 = __shfl_xor_sync(FULL, v0, j);
                unsigned long long p1 = __shfl_xor_sync(FULL, v1, j);
                bool km0 = (lower == up0);
                bool km1 = (lower == up1);
                unsigned long long mn0 = (v0 < p0) ? v0 : p0;
                unsigned long long mx0 = (v0 < p0) ? p0 : v0;
                unsigned long long mn1 = (v1 < p1) ? v1 : p1;
                unsigned long long mx1 = (v1 < p1) ? p1 : v1;
                v0 = km0 ? mn0 : mx0;
                v1 = km1 ? mn1 : mx1;
            }
        }
        keys[tid]       = v0;
        keys[tid + 512] = v1;
        __syncthreads();
    }

    for (int i = tid; i < NPRE; i += 512) {
        unsigned long long kk = keys[i];
        unsigned int hi = (unsigned int)(kk >> 32);
        unsigned int bits = (hi & 0x80000000u) ? (hi ^ 0x80000000u) : ~hi;
        float s = __uint_as_float(bits);
        float e = expf(s);
        g_sorted[b * NPRE + i] = s;
        g_exp[b * NPRE + i]    = e;
        g_se[b * NPRE + i]     = s * e;
        g_idx[b * NPRE + i]    = (int)(kk & 0xFFFFFFFFu);
    }
}

// ---------------------------------------------------------------------------
// Lambert W0 on [-1/e, 0): same clip/init/Halley form as the reference.
// ---------------------------------------------------------------------------
__device__ __forceinline__ float lambertw0_dev(float z)
{
    float zc = fminf(fmaxf(z, -INV_E_F + 1e-8f), -1e-30f);
    float w;
    if (zc < -0.2f)
        w = -1.0f + sqrtf(2.0f * fmaf(E_F, zc, 1.0f));
    else
        w = zc * (1.0f - zc);
    #pragma unroll
    for (int it = 0; it < 6; ++it) {
        float ew  = __expf(w);
        float f   = fmaf(w, ew, -zc);
        float wp1 = w + 1.0f;
        float denom = fmaf(2.0f * ew * wp1, wp1, -(w + 2.0f) * f);
        w = w - __fdividef(f * 2.0f * wp1, denom);
    }
    return w;
}

// ---------------------------------------------------------------------------
// Kernel 2: warp-autonomous chunked causal scan.
//   All metadata (s, e, s*e, idx for the full 1024 sorted inputs) is staged
//   to shared ONCE; single __syncthreads; the main loop has NO barriers.
//   Warp layout: lane = q*4 + nl -> 8 slices x 4 neurons. Per chunk:
//     - slice totals (pa,pb) from register weights (8 FMA pairs)
//     - prefetch next chunk's weights (registers)
//     - segmented inclusive scan over q via 3 shfl_up steps -> exclusive
//       prefix + chunk totals
//     - exact gates per k (a*s_next - b >= e_next, equivalent to
//       z >= -1/e AND t <= s_next), Lambert only on pass (rare)
//     - ballot/ffs/shfl resolves first-valid (min k) per neuron; lane q==0
//       writes the result. Warp exits when its 4 neurons are all done.
// ---------------------------------------------------------------------------
__global__ void __launch_bounds__(NTHR) scan_kernel(const float* __restrict__ Wmat,
                                                    float* __restrict__ out)
{
    __shared__ float sh_s[NPRE + 1];
    __shared__ float sh_e[NPRE + 1];
    __shared__ float sh_se[NPRE];
    __shared__ int   sh_idx[NPRE];

    const int b    = blockIdx.x / NGRP;
    const int grp  = blockIdx.x % NGRP;
    const int tid  = threadIdx.x;
    const int wrp  = tid >> 5;
    const int l    = tid & 31;
    const int q    = l >> 2;            // slice 0..7
    const int nl   = l & 3;             // neuron-in-warp 0..3
    const int ng   = grp * NT + wrp * 4 + nl;   // global output neuron
    const int base = b * NPRE;

    // ---- stage all metadata once ----
    for (int i = tid; i < NPRE; i += NTHR) {
        sh_s[i]   = g_sorted[base + i];
        sh_e[i]   = g_exp[base + i];
        sh_se[i]  = g_se[base + i];
        sh_idx[i] = g_idx[base + i];
    }
    if (tid == 0) { sh_s[NPRE] = INFINITY; sh_e[NPRE] = INFINITY; }
    __syncthreads();

    // ---- prologue: chunk-0 weights ----
    float wv[KSUB];
    #pragma unroll
    for (int kk = 0; kk < KSUB; ++kk)
        wv[kk] = __ldg(&Wmat[sh_idx[q * KSUB + kk] * NPOST + ng]);

    bool  done  = false;
    float a_run = 0.0f, b_run = 0.0f;

    for (int c = 0; c < NCHUNK; ++c) {
        const int kbase = c * CH + q * KSUB;

        // ---- slice totals from register weights ----
        float pa = 0.0f, pb = 0.0f;
        if (!done) {
            #pragma unroll
            for (int kk = 0; kk < KSUB; ++kk) {
                pa = fmaf(wv[kk], sh_e[kbase + kk],  pa);
                pb = fmaf(wv[kk], sh_se[kbase + kk], pb);
            }
        }
        // ---- prefetch next chunk weights ----
        float wn[KSUB];
        if (!done && c + 1 < NCHUNK) {
            #pragma unroll
            for (int kk = 0; kk < KSUB; ++kk)
                wn[kk] = __ldg(&Wmat[sh_idx[(c + 1) * CH + q * KSUB + kk] * NPOST + ng]);
        }

        // ---- segmented inclusive scan over q (stride-4 lanes) ----
        float ia = pa, ib = pb, t0, t1;
        t0 = __shfl_up_sync(FULL, ia, 4);  t1 = __shfl_up_sync(FULL, ib, 4);
        if (q >= 1) { ia += t0; ib += t1; }
        t0 = __shfl_up_sync(FULL, ia, 8);  t1 = __shfl_up_sync(FULL, ib, 8);
        if (q >= 2) { ia += t0; ib += t1; }
        t0 = __shfl_up_sync(FULL, ia, 16); t1 = __shfl_up_sync(FULL, ib, 16);
        if (q >= 4) { ia += t0; ib += t1; }
        float ea = __shfl_up_sync(FULL, ia, 4);   // exclusive prefix
        float eb = __shfl_up_sync(FULL, ib, 4);
        if (q == 0) { ea = 0.0f; eb = 0.0f; }
        float tot_a = __shfl_sync(FULL, ia, 28 + nl);   // q==7 inclusive = chunk total
        float tot_b = __shfl_sync(FULL, ib, 28 + nl);

        // ---- exact gate scan over this slice ----
        bool  found = false;
        float ct    = INFINITY;
        if (!done) {
            float aa = a_run + ea;
            float bb = b_run + eb;
            #pragma unroll
            for (int kk = 0; kk < KSUB; ++kk) {
                if (!found) {
                    int kc = kbase + kk;
                    aa = fmaf(wv[kk], sh_e[kc],  aa);
                    bb = fmaf(wv[kk], sh_se[kc], bb);
                    // exact gate: z >= -1/e AND t <= s_next
                    if (fmaf(aa, sh_s[kc + 1], -bb) >= sh_e[kc + 1]) {
                        float r = __fdividef(bb, aa);
                        float z = -__fdividef(__expf(r), aa);
                        bool valid = (aa > 0.0f) && (z >= -INV_E_F);
                        float t = r - lambertw0_dev(z);
                        if (valid && t >= sh_s[kc]) {   // causal lower bound
                            found = true; ct = t;        // first valid in slice
                        }
                    }
                }
            }
        }

        // ---- per-neuron resolution: lowest-q found lane wins (min k) ----
        unsigned bal = __ballot_sync(FULL, found);
        unsigned gb  = bal & (0x11111111u << nl);
        int src = gb ? (int)(__ffs(gb) - 1) : l;
        float tw = __shfl_sync(FULL, ct, src);
        if (!done) {
            if (gb) {
                done = true;
                if (q == 0) out[b * NPOST + ng] = tw;
            } else {
                a_run += tot_a;
                b_run += tot_b;
            }
        }

        if (__all_sync(FULL, done)) break;   // warp-local early exit

        #pragma unroll
        for (int kk = 0; kk < KSUB; ++kk) wv[kk] = wn[kk];
    }

    if (!done && q == 0) out[b * NPOST + ng] = INFINITY;
}

// ---------------------------------------------------------------------------
extern "C" void kernel_launch(void* const* d_in, const int* in_sizes, int n_in,
                              void* d_out, int out_size)
{
    const float* spikes  = (const float*)d_in[0];
    const float* weights = (const float*)d_in[1];
    int sz = in_sizes[0];
    if (n_in >= 2 && in_sizes[0] > in_sizes[1]) {   // robustness to input order
        const float* t = spikes; spikes = weights; weights = t;
        sz = in_sizes[1];
    }
    int B = sz / NPRE;
    sort_kernel<<<B, 512>>>(spikes);
    scan_kernel<<<B * NGRP, NTHR>>>(weights, (float*)d_out);
}